// round 12
// baseline (speedup 1.0000x reference)
#include <cuda_runtime.h>
#include <cstdint>

// ---------------- configuration ----------------
#define THREADS 128
#define NT0     32           // layer-0 tiles (K=1024, 32 k each)
#define NT_ALL  96           // + 64 layer-1 tiles (K=2048)
#define WTILE   16384        // 128 rows x 128B, XOR-swizzled tf32
#define ZHALF   8192         // 64 rows x 128B per batch

// dynamic smem byte offsets (112KB per CTA -> 2 CTAs/SM)
#define OFF_X   0            // 2 * 8192   x fp32 [32][64] per batch
#define OFF_H   16384        // 2 * 16384  h fp32 [64][64] per batch
#define OFF_W   49152        // 2 * WTILE  (double-buffered W tile)
#define OFF_Z   81920        // 2 * (2*ZHALF) (double-buffered z, both batches)
#define SMEM_TOTAL 114688

// pre-converted, pre-swizzled W: 96 tf32 tiles
__device__ __align__(16) unsigned char g_Wpre[96 * WTILE];

// ---------------- helpers ----------------
static __device__ __forceinline__ uint32_t smem_u32(const void* p) {
    return (uint32_t)__cvta_generic_to_shared(p);
}
static __device__ __forceinline__ void cpa16(uint32_t dst, const void* src) {
    asm volatile("cp.async.cg.shared.global [%0], [%1], 16;" :: "r"(dst), "l"(src));
}
static __device__ __forceinline__ void cp_commit() { asm volatile("cp.async.commit_group;"); }
template <int N>
static __device__ __forceinline__ void cp_wait() { asm volatile("cp.async.wait_group %0;" :: "n"(N)); }

static __device__ __forceinline__ void sts128(uint32_t a, uint32_t r0, uint32_t r1, uint32_t r2, uint32_t r3) {
    asm volatile("st.shared.v4.b32 [%0], {%1, %2, %3, %4};" :: "r"(a), "r"(r0), "r"(r1), "r"(r2), "r"(r3));
}
static __device__ __forceinline__ void ldmx4(uint32_t* r, uint32_t a) {
    asm volatile("ldmatrix.sync.aligned.m8n8.x4.shared.b16 {%0,%1,%2,%3}, [%4];"
        : "=r"(r[0]), "=r"(r[1]), "=r"(r[2]), "=r"(r[3]) : "r"(a));
}
static __device__ __forceinline__ uint32_t f2tf32(float f) {
    uint32_t r; asm("cvt.rna.tf32.f32 %0, %1;" : "=r"(r) : "f"(f)); return r;
}
// m16n8k8 row.col tf32 -> f32, D += A*B (register-pure)
static __device__ __forceinline__ void mma_tf32(float* c, const uint32_t* a, const uint32_t* b) {
    asm("mma.sync.aligned.m16n8k8.row.col.f32.tf32.tf32.f32 "
        "{%0,%1,%2,%3}, {%4,%5,%6,%7}, {%8,%9}, {%0,%1,%2,%3};"
        : "+f"(c[0]), "+f"(c[1]), "+f"(c[2]), "+f"(c[3])
        : "r"(a[0]), "r"(a[1]), "r"(a[2]), "r"(a[3]), "r"(b[0]), "r"(b[1]));
}

// ---------------- prep: round W to tf32, XOR-swizzled 32-k tiles ----------------
__global__ void prep_kernel(const float* __restrict__ W0, const float* __restrict__ W1) {
    int idx = blockIdx.x * 256 + threadIdx.x;      // 0..393215
    float w; int o, k; size_t base;
    if (idx < 131072) { o = idx >> 10; k = idx & 1023; w = W0[idx]; base = (size_t)(k >> 5) * WTILE; }
    else { int j = idx - 131072; o = j >> 11; k = j & 2047; w = W1[j]; base = (size_t)(32 + (k >> 5)) * WTILE; }
    uint32_t c = (uint32_t)((k >> 2) & 7);         // 16B chunk within row
    size_t off = base + (size_t)o * 128 + (size_t)(((c ^ (o & 7)) << 4) + (k & 3) * 4);
    *(uint32_t*)(g_Wpre + off) = f2tf32(w);
}

// ---------------- main kernel ----------------
__global__ __launch_bounds__(THREADS, 2)
void cin_mma_kernel(const float* __restrict__ xg,
                    const float* __restrict__ b0g,
                    const float* __restrict__ b1g,
                    float* __restrict__ out)
{
    extern __shared__ __align__(256) unsigned char smem[];
    const uint32_t sb = smem_u32(smem);
    const int tid  = threadIdx.x;
    const int wid  = tid >> 5;
    const int lane = tid & 31;
    const int lr   = lane >> 2;
    const int lc   = lane & 3;

    const int bz = wid >> 1;        // warp's batch (0/1)
    const int oh = wid & 1;         // warp o-half -> o base oh*64

    // swizzled ldmatrix addressing
    const uint32_t l7  = (uint32_t)(lane & 7);
    const uint32_t aHi = (uint32_t)((lane >> 4) & 1);
    const uint32_t bHi = (uint32_t)((lane >> 3) & 1);
    const uint32_t aRowOff = (uint32_t)((oh * 64 + (lane & 15)) * 128);
    const uint32_t bRowOff = (uint32_t)(((lane & 7) + ((lane & 16) >> 1)) * 128);

    float* xs = (float*)(smem + OFF_X);
    float* hs = (float*)(smem + OFF_H);

    const int bbase = blockIdx.x * 2;

    // initial loads: x (16KB) + W tile 0 (16KB), 8+8 chunks/thread
    {
        const char* src = (const char*)(xg + (size_t)bbase * 2048);
        #pragma unroll
        for (int r = 0; r < 8; r++)
            cpa16(sb + OFF_X + (uint32_t)(r * THREADS + tid) * 16, src + (size_t)(r * THREADS + tid) * 16);
        #pragma unroll
        for (int r = 0; r < 8; r++)
            cpa16(sb + OFF_W + (uint32_t)(r * THREADS + tid) * 16, g_Wpre + (size_t)(r * THREADS + tid) * 16);
        cp_commit();
    }

    // z producer mapping: thread -> (batch bzt, d), all 32 m
    const int d   = tid & 63;
    const int bzt = tid >> 6;
    const uint32_t d7 = (uint32_t)(d & 7);

    cp_wait<0>();
    __syncthreads();

    // register-cached x values (loop-invariant across both layers)
    float xmc[32];
    #pragma unroll
    for (int j = 0; j < 32; j++) xmc[j] = xs[bzt * 2048 + j * 64 + d];

    // build z tile j (both batches), buffer j&1, xh passed in a register.
    // Chunked (4 values -> sts128) to keep transient register count low.
    auto build_z = [&](int j, float xh) {
        const uint32_t zb = sb + OFF_Z + (uint32_t)(j & 1) * (2 * ZHALF) + (uint32_t)bzt * ZHALF
                          + (uint32_t)(d * 128);
        #pragma unroll
        for (int c4 = 0; c4 < 8; c4++) {
            uint32_t t0 = f2tf32(xh * xmc[4 * c4 + 0]);
            uint32_t t1 = f2tf32(xh * xmc[4 * c4 + 1]);
            uint32_t t2 = f2tf32(xh * xmc[4 * c4 + 2]);
            uint32_t t3 = f2tf32(xh * xmc[4 * c4 + 3]);
            sts128(zb + (((uint32_t)c4 ^ d7) << 4), t0, t1, t2, t3);
        }
    };

    float acc[4][8][4];             // [mi][nj][q] — statically indexed, 128 regs
    #pragma unroll
    for (int mi = 0; mi < 4; mi++)
        #pragma unroll
        for (int nj = 0; nj < 8; nj++)
            #pragma unroll
            for (int q = 0; q < 4; q++) acc[mi][nj][q] = 0.0f;

    build_z(0, xs[bzt * 2048 + d]);                 // tile 0 (h-row 0)
    float xh_next = xs[bzt * 2048 + 64 + d];        // xh for tile 1

    for (int g = 0; g < NT_ALL; g++) {
        if (g > 0) cp_wait<0>();          // W(g) resident
        __syncthreads();                  // z(g) visible; z(g-1) readers done

        const uint32_t wbuf = sb + OFF_W + (uint32_t)(g & 1) * WTILE;
        const uint32_t aA   = wbuf + aRowOff;
        const uint32_t bB   = sb + OFF_Z + (uint32_t)(g & 1) * (2 * ZHALF)
                            + (uint32_t)bz * ZHALF + bRowOff;

        // ---- MMA block FIRST: fragment loads are the first volatile ops
        // after the barrier, so the tensor pipe is fed immediately.
        {
            // ks = 0
            uint32_t A[4][4], B[4][4];
            {
                const uint32_t swA = (aHi ^ l7) << 4;
                const uint32_t swB = (bHi ^ l7) << 4;
                #pragma unroll
                for (int t4 = 0; t4 < 4; t4++) ldmx4(A[t4], aA + (uint32_t)(t4 * 2048) + swA);
                #pragma unroll
                for (int t4 = 0; t4 < 4; t4++) ldmx4(B[t4], bB + (uint32_t)(t4 * 2048) + swB);
            }

            // W(g+1) prefetch: async issue, lands well before next cp_wait
            if (g + 1 < NT_ALL) {
                const unsigned char* src = g_Wpre + (size_t)(g + 1) * WTILE;
                uint32_t dst = sb + OFF_W + (uint32_t)((g + 1) & 1) * WTILE;
                #pragma unroll
                for (int r = 0; r < 8; r++)
                    cpa16(dst + (uint32_t)(r * THREADS + tid) * 16, src + (size_t)(r * THREADS + tid) * 16);
                cp_commit();
            }

            #pragma unroll
            for (int mi = 0; mi < 4; mi++)
                #pragma unroll
                for (int t4 = 0; t4 < 4; t4++) {
                    mma_tf32(acc[mi][2*t4],     A[mi], B[t4]);
                    mma_tf32(acc[mi][2*t4 + 1], A[mi], B[t4] + 2);
                }

            // ks = 1..3
            #pragma unroll
            for (uint32_t ks = 1; ks < 4; ks++) {
                const uint32_t swA = (((ks << 1) | aHi) ^ l7) << 4;
                const uint32_t swB = (((ks << 1) | bHi) ^ l7) << 4;
                #pragma unroll
                for (int t4 = 0; t4 < 4; t4++) ldmx4(A[t4], aA + (uint32_t)(t4 * 2048) + swA);
                #pragma unroll
                for (int t4 = 0; t4 < 4; t4++) ldmx4(B[t4], bB + (uint32_t)(t4 * 2048) + swB);
                #pragma unroll
                for (int mi = 0; mi < 4; mi++)
                    #pragma unroll
                    for (int t4 = 0; t4 < 4; t4++) {
                        mma_tf32(acc[mi][2*t4],     A[mi], B[t4]);
                        mma_tf32(acc[mi][2*t4 + 1], A[mi], B[t4] + 2);
                    }
            }
        }

        // ---- build z(g+1) AFTER the MMA block: its ALU/CVT/STS work executes
        // while the 128-deep mma stream drains on the tensor pipe.
        if (g + 1 < NT_ALL && g != NT0 - 1) build_z(g + 1, xh_next);

        // prefetch xh for tile g+2 (layer-transition tiles handled in epilogue)
        {
            const int t = g + 2;
            if (t < NT0)            xh_next = xs[bzt * 2048 + t * 64 + d];
            else if (g >= NT0 && t < NT_ALL)
                                    xh_next = hs[bzt * 4096 + (t - NT0) * 64 + d];
        }

        if (g == NT0 - 1) {
            // ======== layer-0 epilogue ========
            __syncthreads();              // all layer-0 MMA smem reads done
            #pragma unroll
            for (int mi = 0; mi < 4; mi++) {
                const int o = oh * 64 + mi * 16 + lr;
                const float bias0 = b0g[o], bias1 = b0g[o + 8];
                if (oh == 0) {            // rows 0..63 -> h
                    float* h0 = hs + bz * 4096 + o * 64;
                    float* h1 = h0 + 8 * 64;
                    #pragma unroll
                    for (int nj = 0; nj < 8; nj++) {
                        const int dd = nj * 8 + 2 * lc;
                        h0[dd]     = fmaxf(acc[mi][nj][0] + bias0, 0.0f);
                        h0[dd + 1] = fmaxf(acc[mi][nj][1] + bias0, 0.0f);
                        h1[dd]     = fmaxf(acc[mi][nj][2] + bias1, 0.0f);
                        h1[dd + 1] = fmaxf(acc[mi][nj][3] + bias1, 0.0f);
                    }
                } else {                  // rows 64..127 -> out rows 0..63
                    float s0 = 0.0f, s1 = 0.0f;
                    #pragma unroll
                    for (int nj = 0; nj < 8; nj++) {
                        s0 += fmaxf(acc[mi][nj][0] + bias0, 0.0f)
                            + fmaxf(acc[mi][nj][1] + bias0, 0.0f);
                        s1 += fmaxf(acc[mi][nj][2] + bias1, 0.0f)
                            + fmaxf(acc[mi][nj][3] + bias1, 0.0f);
                    }
                    s0 += __shfl_xor_sync(0xffffffffu, s0, 1);
                    s0 += __shfl_xor_sync(0xffffffffu, s0, 2);
                    s1 += __shfl_xor_sync(0xffffffffu, s1, 1);
                    s1 += __shfl_xor_sync(0xffffffffu, s1, 2);
                    if (lc == 0) {
                        out[(size_t)(bbase + bz) * 192 + (o - 64)]     = s0;
                        out[(size_t)(bbase + bz) * 192 + (o - 64) + 8] = s1;
                    }
                }
            }
            #pragma unroll
            for (int mi = 0; mi < 4; mi++)
                #pragma unroll
                for (int nj = 0; nj < 8; nj++)
                    #pragma unroll
                    for (int q = 0; q < 4; q++) acc[mi][nj][q] = 0.0f;
            __syncthreads();              // h complete before z(32) reads it
            build_z(NT0, hs[bzt * 4096 + d]);            // tile NT0 (h-row 0)
            xh_next = hs[bzt * 4096 + 64 + d];           // xh for tile NT0+1
        }
    }

    // ======== layer-1 epilogue: out rows 64..191, direct ========
    #pragma unroll
    for (int mi = 0; mi < 4; mi++) {
        const int o = oh * 64 + mi * 16 + lr;
        const float bias0 = b1g[o], bias1 = b1g[o + 8];
        float s0 = 0.0f, s1 = 0.0f;
        #pragma unroll
        for (int nj = 0; nj < 8; nj++) {
            s0 += fmaxf(acc[mi][nj][0] + bias0, 0.0f)
                + fmaxf(acc[mi][nj][1] + bias0, 0.0f);
            s1 += fmaxf(acc[mi][nj][2] + bias1, 0.0f)
                + fmaxf(acc[mi][nj][3] + bias1, 0.0f);
        }
        s0 += __shfl_xor_sync(0xffffffffu, s0, 1);
        s0 += __shfl_xor_sync(0xffffffffu, s0, 2);
        s1 += __shfl_xor_sync(0xffffffffu, s1, 1);
        s1 += __shfl_xor_sync(0xffffffffu, s1, 2);
        if (lc == 0) {
            out[(size_t)(bbase + bz) * 192 + 64 + o]     = s0;
            out[(size_t)(bbase + bz) * 192 + 64 + o + 8] = s1;
        }
    }
}

// ---------------- launch ----------------
extern "C" void kernel_launch(void* const* d_in, const int* in_sizes, int n_in,
                              void* d_out, int out_size) {
    const float* xg = (const float*)d_in[0];   // (2048,32,64)
    const float* W0 = (const float*)d_in[1];   // (128,1024)
    const float* b0 = (const float*)d_in[2];   // (128)
    const float* W1 = (const float*)d_in[3];   // (128,2048)
    const float* b1 = (const float*)d_in[4];   // (128)
    float* out = (float*)d_out;                // (2048,192)

    prep_kernel<<<1536, 256>>>(W0, W1);

    cudaFuncSetAttribute((const void*)cin_mma_kernel,
                         cudaFuncAttributeMaxDynamicSharedMemorySize, SMEM_TOTAL);
    cin_mma_kernel<<<1024, THREADS, SMEM_TOTAL>>>(xg, b0, b1, out);
}

// round 13
// speedup vs baseline: 1.0593x; 1.0593x over previous
#include <cuda_runtime.h>
#include <cstdint>

// ---------------- configuration ----------------
#define THREADS 128
#define NT0     32           // layer-0 tiles (K=1024, 32 k each)
#define NT_ALL  96           // + 64 layer-1 tiles (K=2048)
#define WTILE   16384        // 128 rows x 128B, XOR-swizzled tf32
#define ZHALF   8192         // 64 rows x 128B per batch
#define GRID_FULL 888        // NB=2 CTAs (3 clean waves on 148 SMs)
#define GRID_TAIL 272        // NB=1 CTAs (tail wave)

// dynamic smem byte offsets (112KB per CTA -> 2 CTAs/SM)
#define OFF_X   0            // 2 * 8192   x fp32 [32][64] per batch
#define OFF_H   16384        // 2 * 16384  h fp32 [64][64] per batch
#define OFF_W   49152        // 2 * WTILE  (double-buffered W tile)
#define OFF_Z   81920        // 2 * (2*ZHALF) (double-buffered z, both batches)
#define SMEM_TOTAL 114688

// pre-converted, pre-swizzled W: 96 tf32 tiles
__device__ __align__(16) unsigned char g_Wpre[96 * WTILE];

// ---------------- helpers ----------------
static __device__ __forceinline__ uint32_t smem_u32(const void* p) {
    return (uint32_t)__cvta_generic_to_shared(p);
}
static __device__ __forceinline__ void cpa16(uint32_t dst, const void* src) {
    asm volatile("cp.async.cg.shared.global [%0], [%1], 16;" :: "r"(dst), "l"(src));
}
static __device__ __forceinline__ void cp_commit() { asm volatile("cp.async.commit_group;"); }
template <int N>
static __device__ __forceinline__ void cp_wait() { asm volatile("cp.async.wait_group %0;" :: "n"(N)); }

static __device__ __forceinline__ void sts128(uint32_t a, uint32_t r0, uint32_t r1, uint32_t r2, uint32_t r3) {
    asm volatile("st.shared.v4.b32 [%0], {%1, %2, %3, %4};" :: "r"(a), "r"(r0), "r"(r1), "r"(r2), "r"(r3));
}
static __device__ __forceinline__ void ldmx4(uint32_t* r, uint32_t a) {
    asm volatile("ldmatrix.sync.aligned.m8n8.x4.shared.b16 {%0,%1,%2,%3}, [%4];"
        : "=r"(r[0]), "=r"(r[1]), "=r"(r[2]), "=r"(r[3]) : "r"(a));
}
static __device__ __forceinline__ uint32_t f2tf32(float f) {
    uint32_t r; asm("cvt.rna.tf32.f32 %0, %1;" : "=r"(r) : "f"(f)); return r;
}
// m16n8k8 row.col tf32 -> f32, D += A*B (register-pure)
static __device__ __forceinline__ void mma_tf32(float* c, const uint32_t* a, const uint32_t* b) {
    asm("mma.sync.aligned.m16n8k8.row.col.f32.tf32.tf32.f32 "
        "{%0,%1,%2,%3}, {%4,%5,%6,%7}, {%8,%9}, {%0,%1,%2,%3};"
        : "+f"(c[0]), "+f"(c[1]), "+f"(c[2]), "+f"(c[3])
        : "r"(a[0]), "r"(a[1]), "r"(a[2]), "r"(a[3]), "r"(b[0]), "r"(b[1]));
}

// ---------------- prep: round W to tf32, XOR-swizzled 32-k tiles ----------------
__global__ void prep_kernel(const float* __restrict__ W0, const float* __restrict__ W1) {
    int idx = blockIdx.x * 256 + threadIdx.x;      // 0..393215
    float w; int o, k; size_t base;
    if (idx < 131072) { o = idx >> 10; k = idx & 1023; w = W0[idx]; base = (size_t)(k >> 5) * WTILE; }
    else { int j = idx - 131072; o = j >> 11; k = j & 2047; w = W1[j]; base = (size_t)(32 + (k >> 5)) * WTILE; }
    uint32_t c = (uint32_t)((k >> 2) & 7);         // 16B chunk within row
    size_t off = base + (size_t)o * 128 + (size_t)(((c ^ (o & 7)) << 4) + (k & 3) * 4);
    *(uint32_t*)(g_Wpre + off) = f2tf32(w);
}

// ---------------- body (R10 structure, templatized on batches-per-CTA) ----------------
template <int NBATCH>
static __device__ __forceinline__ void cin_body(
    const float* __restrict__ xg, const float* __restrict__ b0g,
    const float* __restrict__ b1g, float* __restrict__ out,
    int bbase, unsigned char* smem, uint32_t sb)
{
    constexpr int MI = 2 * NBATCH;      // 16-row acc tiles per warp
    const int tid  = threadIdx.x;
    const int wid  = tid >> 5;
    const int lane = tid & 31;
    const int lr   = lane >> 2;
    const int lc   = lane & 3;

    const int bz    = (NBATCH == 2) ? (wid >> 1) : 0;       // warp's batch
    const int obase = (NBATCH == 2) ? ((wid & 1) * 64) : (wid * 32);

    // swizzled ldmatrix addressing
    const uint32_t l7  = (uint32_t)(lane & 7);
    const uint32_t aHi = (uint32_t)((lane >> 4) & 1);
    const uint32_t bHi = (uint32_t)((lane >> 3) & 1);
    const uint32_t aRowOff = (uint32_t)((obase + (lane & 15)) * 128);
    const uint32_t bRowOff = (uint32_t)(((lane & 7) + ((lane & 16) >> 1)) * 128);

    float* xs = (float*)(smem + OFF_X);
    float* hs = (float*)(smem + OFF_H);

    // initial loads: x (NBATCH*8KB) + W tile 0 (16KB)
    {
        const char* src = (const char*)(xg + (size_t)bbase * 2048);
        #pragma unroll
        for (int r = 0; r < NBATCH * 4; r++)
            cpa16(sb + OFF_X + (uint32_t)(r * THREADS + tid) * 16, src + (size_t)(r * THREADS + tid) * 16);
        #pragma unroll
        for (int r = 0; r < 8; r++)
            cpa16(sb + OFF_W + (uint32_t)(r * THREADS + tid) * 16, g_Wpre + (size_t)(r * THREADS + tid) * 16);
        cp_commit();
    }

    // z producer mapping: thread -> (batch bzt, d), all 32 m
    const int d   = tid & 63;
    const int bzt = (NBATCH == 2) ? (tid >> 6) : 0;
    const bool zact = (NBATCH == 2) || (tid < 64);
    const uint32_t d7 = (uint32_t)(d & 7);

    cp_wait<0>();
    __syncthreads();

    // register-cached x values (loop-invariant across both layers)
    float xmc[32];
    if (zact) {
        #pragma unroll
        for (int j = 0; j < 32; j++) xmc[j] = xs[bzt * 2048 + j * 64 + d];
    }

    // build z tile j, buffer j&1 (reads xh from smem; R10 form). Never touches acc.
    auto build_z = [&](int j) {
        if (!zact) return;
        const uint32_t zb = sb + OFF_Z + (uint32_t)(j & 1) * (2 * ZHALF) + (uint32_t)bzt * ZHALF
                          + (uint32_t)(d * 128);
        const float xh = (j < NT0) ? xs[bzt * 2048 + j * 64 + d]
                                   : hs[bzt * 4096 + (j - NT0) * 64 + d];
        uint32_t t[32];
        #pragma unroll
        for (int jj = 0; jj < 32; jj++) t[jj] = f2tf32(xh * xmc[jj]);
        #pragma unroll
        for (int c4 = 0; c4 < 8; c4++)
            sts128(zb + (((uint32_t)c4 ^ d7) << 4), t[4*c4], t[4*c4+1], t[4*c4+2], t[4*c4+3]);
    };

    float acc[MI][8][4];            // statically indexed
    #pragma unroll
    for (int mi = 0; mi < MI; mi++)
        #pragma unroll
        for (int nj = 0; nj < 8; nj++)
            #pragma unroll
            for (int q = 0; q < 4; q++) acc[mi][nj][q] = 0.0f;

    build_z(0);

    for (int g = 0; g < NT_ALL; g++) {
        if (g > 0) cp_wait<0>();          // W(g) resident
        __syncthreads();                  // z(g) visible; z(g-1) readers done

        if (g + 1 < NT_ALL && g != NT0 - 1) build_z(g + 1);

        if (g + 1 < NT_ALL) {             // prefetch next W tile (8 chunks/thread)
            const unsigned char* src = g_Wpre + (size_t)(g + 1) * WTILE;
            uint32_t dst = sb + OFF_W + (uint32_t)((g + 1) & 1) * WTILE;
            #pragma unroll
            for (int r = 0; r < 8; r++)
                cpa16(dst + (uint32_t)(r * THREADS + tid) * 16, src + (size_t)(r * THREADS + tid) * 16);
            cp_commit();
        }

        // ---- MMA: warp = (batch bz, obase): MI*16 o x 64 d x 32 k
        {
            const uint32_t wbuf = sb + OFF_W + (uint32_t)(g & 1) * WTILE;
            const uint32_t aA   = wbuf + aRowOff;
            const uint32_t bB   = sb + OFF_Z + (uint32_t)(g & 1) * (2 * ZHALF)
                                + (uint32_t)bz * ZHALF + bRowOff;
            #pragma unroll
            for (uint32_t ks = 0; ks < 4; ks++) {
                uint32_t A[MI][4], B[4][4];
                const uint32_t swA = (((ks << 1) | aHi) ^ l7) << 4;
                const uint32_t swB = (((ks << 1) | bHi) ^ l7) << 4;
                #pragma unroll
                for (int t4 = 0; t4 < MI; t4++) ldmx4(A[t4], aA + (uint32_t)(t4 * 2048) + swA);
                #pragma unroll
                for (int t4 = 0; t4 < 4; t4++) ldmx4(B[t4], bB + (uint32_t)(t4 * 2048) + swB);
                #pragma unroll
                for (int mi = 0; mi < MI; mi++)
                    #pragma unroll
                    for (int t4 = 0; t4 < 4; t4++) {
                        mma_tf32(acc[mi][2*t4],     A[mi], B[t4]);
                        mma_tf32(acc[mi][2*t4 + 1], A[mi], B[t4] + 2);
                    }
            }
        }

        if (g == NT0 - 1) {
            // ======== layer-0 epilogue ========
            __syncthreads();              // all layer-0 MMA smem reads done
            #pragma unroll
            for (int mi = 0; mi < MI; mi++) {
                const int o = obase + mi * 16 + lr;
                const float bias0 = b0g[o], bias1 = b0g[o + 8];
                if (obase + mi * 16 < 64) {   // rows 0..63 -> h (warp-uniform)
                    float* h0 = hs + bz * 4096 + o * 64;
                    float* h1 = h0 + 8 * 64;
                    #pragma unroll
                    for (int nj = 0; nj < 8; nj++) {
                        const int dd = nj * 8 + 2 * lc;
                        h0[dd]     = fmaxf(acc[mi][nj][0] + bias0, 0.0f);
                        h0[dd + 1] = fmaxf(acc[mi][nj][1] + bias0, 0.0f);
                        h1[dd]     = fmaxf(acc[mi][nj][2] + bias1, 0.0f);
                        h1[dd + 1] = fmaxf(acc[mi][nj][3] + bias1, 0.0f);
                    }
                } else {                  // rows 64..127 -> out rows 0..63
                    float s0 = 0.0f, s1 = 0.0f;
                    #pragma unroll
                    for (int nj = 0; nj < 8; nj++) {
                        s0 += fmaxf(acc[mi][nj][0] + bias0, 0.0f)
                            + fmaxf(acc[mi][nj][1] + bias0, 0.0f);
                        s1 += fmaxf(acc[mi][nj][2] + bias1, 0.0f)
                            + fmaxf(acc[mi][nj][3] + bias1, 0.0f);
                    }
                    s0 += __shfl_xor_sync(0xffffffffu, s0, 1);
                    s0 += __shfl_xor_sync(0xffffffffu, s0, 2);
                    s1 += __shfl_xor_sync(0xffffffffu, s1, 1);
                    s1 += __shfl_xor_sync(0xffffffffu, s1, 2);
                    if (lc == 0) {
                        out[(size_t)(bbase + bz) * 192 + (o - 64)]     = s0;
                        out[(size_t)(bbase + bz) * 192 + (o - 64) + 8] = s1;
                    }
                }
            }
            #pragma unroll
            for (int mi = 0; mi < MI; mi++)
                #pragma unroll
                for (int nj = 0; nj < 8; nj++)
                    #pragma unroll
                    for (int q = 0; q < 4; q++) acc[mi][nj][q] = 0.0f;
            __syncthreads();              // h complete before z(32) reads it
            build_z(NT0);                 // into buf 0 (last read by MMA(30))
        }
    }

    // ======== layer-1 epilogue: out rows 64..191, direct ========
    #pragma unroll
    for (int mi = 0; mi < MI; mi++) {
        const int o = obase + mi * 16 + lr;
        const float bias0 = b1g[o], bias1 = b1g[o + 8];
        float s0 = 0.0f, s1 = 0.0f;
        #pragma unroll
        for (int nj = 0; nj < 8; nj++) {
            s0 += fmaxf(acc[mi][nj][0] + bias0, 0.0f)
                + fmaxf(acc[mi][nj][1] + bias0, 0.0f);
            s1 += fmaxf(acc[mi][nj][2] + bias1, 0.0f)
                + fmaxf(acc[mi][nj][3] + bias1, 0.0f);
        }
        s0 += __shfl_xor_sync(0xffffffffu, s0, 1);
        s0 += __shfl_xor_sync(0xffffffffu, s0, 2);
        s1 += __shfl_xor_sync(0xffffffffu, s1, 1);
        s1 += __shfl_xor_sync(0xffffffffu, s1, 2);
        if (lc == 0) {
            out[(size_t)(bbase + bz) * 192 + 64 + o]     = s0;
            out[(size_t)(bbase + bz) * 192 + 64 + o + 8] = s1;
        }
    }
}

// ---------------- main kernel: mixed-size grid (tail-wave fill) ----------------
__global__ __launch_bounds__(THREADS, 2)
void cin_mma_kernel(const float* __restrict__ xg,
                    const float* __restrict__ b0g,
                    const float* __restrict__ b1g,
                    float* __restrict__ out)
{
    extern __shared__ __align__(256) unsigned char smem[];
    const uint32_t sb = smem_u32(smem);
    const int bid = blockIdx.x;
    if (bid < GRID_FULL) {
        cin_body<2>(xg, b0g, b1g, out, bid * 2, smem, sb);
    } else {
        cin_body<1>(xg, b0g, b1g, out, GRID_FULL * 2 + (bid - GRID_FULL), smem, sb);
    }
}

// ---------------- launch ----------------
extern "C" void kernel_launch(void* const* d_in, const int* in_sizes, int n_in,
                              void* d_out, int out_size) {
    const float* xg = (const float*)d_in[0];   // (2048,32,64)
    const float* W0 = (const float*)d_in[1];   // (128,1024)
    const float* b0 = (const float*)d_in[2];   // (128)
    const float* W1 = (const float*)d_in[3];   // (128,2048)
    const float* b1 = (const float*)d_in[4];   // (128)
    float* out = (float*)d_out;                // (2048,192)

    prep_kernel<<<1536, 256>>>(W0, W1);

    cudaFuncSetAttribute((const void*)cin_mma_kernel,
                         cudaFuncAttributeMaxDynamicSharedMemorySize, SMEM_TOTAL);
    cin_mma_kernel<<<GRID_FULL + GRID_TAIL, THREADS, SMEM_TOTAL>>>(xg, b0, b1, out);
}

// round 14
// speedup vs baseline: 1.1856x; 1.1192x over previous
#include <cuda_runtime.h>
#include <cstdint>

// ---------------- configuration ----------------
#define THREADS 128
#define NT0     20           // layer-0 tiles (folded K=640, 32 k each)
#define NT_ALL  84           // + 64 layer-1 tiles (K=2048)
#define WTILE   16384        // 128 rows x 128B, XOR-swizzled tf32
#define ZHALF   8192         // 64 rows x 128B per batch
#define GRID_FULL 888        // NB=2 CTAs (3 clean waves on 148 SMs)
#define GRID_TAIL 272        // NB=1 CTAs (tail wave)

// dynamic smem byte offsets (112KB per CTA -> 2 CTAs/SM)
#define OFF_X   0            // 2 * 8192   x fp32 [32][64] per batch
#define OFF_H   16384        // 2 * 16384  h fp32 [64][64] per batch
#define OFF_W   49152        // 2 * WTILE  (double-buffered W tile)
#define OFF_Z   81920        // 2 * (2*ZHALF) (double-buffered z, both batches)
#define SMEM_TOTAL 114688

// pre-converted, pre-swizzled W: 84 tf32 tiles (layer-0 symmetry-folded)
__device__ __align__(16) unsigned char g_Wpre[NT_ALL * WTILE];

// block-pair list for folded layer 0 (4 diag + 6 off-diag pairs of 8x8 blocks)
__constant__ int c_bi[10] = {0, 1, 2, 3, 0, 0, 0, 1, 1, 2};
__constant__ int c_bj[10] = {0, 1, 2, 3, 1, 2, 3, 2, 3, 3};

// ---------------- helpers ----------------
static __device__ __forceinline__ uint32_t smem_u32(const void* p) {
    return (uint32_t)__cvta_generic_to_shared(p);
}
static __device__ __forceinline__ void cpa16(uint32_t dst, const void* src) {
    asm volatile("cp.async.cg.shared.global [%0], [%1], 16;" :: "r"(dst), "l"(src));
}
static __device__ __forceinline__ void cp_commit() { asm volatile("cp.async.commit_group;"); }
template <int N>
static __device__ __forceinline__ void cp_wait() { asm volatile("cp.async.wait_group %0;" :: "n"(N)); }

static __device__ __forceinline__ void sts128(uint32_t a, uint32_t r0, uint32_t r1, uint32_t r2, uint32_t r3) {
    asm volatile("st.shared.v4.b32 [%0], {%1, %2, %3, %4};" :: "r"(a), "r"(r0), "r"(r1), "r"(r2), "r"(r3));
}
static __device__ __forceinline__ void ldmx4(uint32_t* r, uint32_t a) {
    asm volatile("ldmatrix.sync.aligned.m8n8.x4.shared.b16 {%0,%1,%2,%3}, [%4];"
        : "=r"(r[0]), "=r"(r[1]), "=r"(r[2]), "=r"(r[3]) : "r"(a));
}
static __device__ __forceinline__ uint32_t f2tf32(float f) {
    uint32_t r; asm("cvt.rna.tf32.f32 %0, %1;" : "=r"(r) : "f"(f)); return r;
}
// m16n8k8 row.col tf32 -> f32, D += A*B (register-pure)
static __device__ __forceinline__ void mma_tf32(float* c, const uint32_t* a, const uint32_t* b) {
    asm("mma.sync.aligned.m16n8k8.row.col.f32.tf32.tf32.f32 "
        "{%0,%1,%2,%3}, {%4,%5,%6,%7}, {%8,%9}, {%0,%1,%2,%3};"
        : "+f"(c[0]), "+f"(c[1]), "+f"(c[2]), "+f"(c[3])
        : "r"(a[0]), "r"(a[1]), "r"(a[2]), "r"(a[3]), "r"(b[0]), "r"(b[1]));
}

// ---------------- prep: fold L0 by symmetry, round to tf32, swizzle ----------------
// L0 slot mapping (tile t<20, slot s): bi=t>>1, half=t&1,
//   h = 8*c_bi[bi] + 4*half + (s>>3), m = 8*c_bj[bi] + (s&7)
//   W'[o,t,s] = W0[o,h*32+m] + (i!=j ? W0[o,m*32+h] : 0)
__global__ void prep_kernel(const float* __restrict__ W0, const float* __restrict__ W1) {
    int idx = blockIdx.x * 256 + threadIdx.x;      // 0..344063
    if (idx >= 344064) return;
    float w; int o, t, s;
    if (idx < 81920) {                  // layer 0 folded: 128 o x 640 k
        o = idx / 640;
        int k = idx - o * 640;
        t = k >> 5; s = k & 31;
        int bi = t >> 1, half = t & 1;
        int i = c_bi[bi], j = c_bj[bi];
        int h = 8 * i + 4 * half + (s >> 3);
        int m = 8 * j + (s & 7);
        w = W0[o * 1024 + h * 32 + m];
        if (i != j) w += W0[o * 1024 + m * 32 + h];
    } else {                            // layer 1: 128 o x 2048 k
        int idx2 = idx - 81920;
        o = idx2 >> 11;
        int k = idx2 & 2047;
        t = NT0 + (k >> 5); s = k & 31;
        w = W1[o * 2048 + k];
    }
    uint32_t c = (uint32_t)((s >> 2) & 7);         // 16B chunk within row
    size_t off = (size_t)t * WTILE + (size_t)o * 128
               + (size_t)(((c ^ (o & 7)) << 4) + (s & 3) * 4);
    *(uint32_t*)(g_Wpre + off) = f2tf32(w);
}

// ---------------- body (R13 structure, folded layer 0) ----------------
template <int NBATCH>
static __device__ __forceinline__ void cin_body(
    const float* __restrict__ xg, const float* __restrict__ b0g,
    const float* __restrict__ b1g, float* __restrict__ out,
    int bbase, unsigned char* smem, uint32_t sb)
{
    constexpr int MI = 2 * NBATCH;      // 16-row acc tiles per warp
    const int tid  = threadIdx.x;
    const int wid  = tid >> 5;
    const int lane = tid & 31;
    const int lr   = lane >> 2;
    const int lc   = lane & 3;

    const int bz    = (NBATCH == 2) ? (wid >> 1) : 0;       // warp's batch
    const int obase = (NBATCH == 2) ? ((wid & 1) * 64) : (wid * 32);

    // swizzled ldmatrix addressing
    const uint32_t l7  = (uint32_t)(lane & 7);
    const uint32_t aHi = (uint32_t)((lane >> 4) & 1);
    const uint32_t bHi = (uint32_t)((lane >> 3) & 1);
    const uint32_t aRowOff = (uint32_t)((obase + (lane & 15)) * 128);
    const uint32_t bRowOff = (uint32_t)(((lane & 7) + ((lane & 16) >> 1)) * 128);

    float* xs = (float*)(smem + OFF_X);
    float* hs = (float*)(smem + OFF_H);

    // initial loads: x (NBATCH*8KB) + W tile 0 (16KB)
    {
        const char* src = (const char*)(xg + (size_t)bbase * 2048);
        #pragma unroll
        for (int r = 0; r < NBATCH * 4; r++)
            cpa16(sb + OFF_X + (uint32_t)(r * THREADS + tid) * 16, src + (size_t)(r * THREADS + tid) * 16);
        #pragma unroll
        for (int r = 0; r < 8; r++)
            cpa16(sb + OFF_W + (uint32_t)(r * THREADS + tid) * 16, g_Wpre + (size_t)(r * THREADS + tid) * 16);
        cp_commit();
    }

    // z producer mapping: thread -> (batch bzt, d)
    const int d   = tid & 63;
    const int bzt = (NBATCH == 2) ? (tid >> 6) : 0;
    const bool zact = (NBATCH == 2) || (tid < 64);
    const uint32_t d7 = (uint32_t)(d & 7);

    cp_wait<0>();
    __syncthreads();

    // register-cached x values (used by layer-1 z-build)
    float xmc[32];
    if (zact) {
        #pragma unroll
        for (int j = 0; j < 32; j++) xmc[j] = xs[bzt * 2048 + j * 64 + d];
    }

    // build z tile j, buffer j&1. Never touches acc.
    auto build_z = [&](int j) {
        if (!zact) return;
        const uint32_t zb = sb + OFF_Z + (uint32_t)(j & 1) * (2 * ZHALF) + (uint32_t)bzt * ZHALF
                          + (uint32_t)(d * 128);
        uint32_t t[32];
        if (j < NT0) {
            // folded layer-0 tile: slot s -> (h,m) pair product
            int bi = j >> 1, half = j & 1;
            int hb = 8 * c_bi[bi] + 4 * half;
            int mb = 8 * c_bj[bi];
            float xh[4], xm[8];
            #pragma unroll
            for (int r = 0; r < 4; r++) xh[r] = xs[bzt * 2048 + (hb + r) * 64 + d];
            #pragma unroll
            for (int c = 0; c < 8; c++) xm[c] = xs[bzt * 2048 + (mb + c) * 64 + d];
            #pragma unroll
            for (int s = 0; s < 32; s++) t[s] = f2tf32(xh[s >> 3] * xm[s & 7]);
        } else {
            // layer-1 tile: h-row (j-NT0) x all 32 m
            const float xh = hs[bzt * 4096 + (j - NT0) * 64 + d];
            #pragma unroll
            for (int jj = 0; jj < 32; jj++) t[jj] = f2tf32(xh * xmc[jj]);
        }
        #pragma unroll
        for (int c4 = 0; c4 < 8; c4++)
            sts128(zb + (((uint32_t)c4 ^ d7) << 4), t[4*c4], t[4*c4+1], t[4*c4+2], t[4*c4+3]);
    };

    float acc[MI][8][4];            // statically indexed
    #pragma unroll
    for (int mi = 0; mi < MI; mi++)
        #pragma unroll
        for (int nj = 0; nj < 8; nj++)
            #pragma unroll
            for (int q = 0; q < 4; q++) acc[mi][nj][q] = 0.0f;

    build_z(0);

    for (int g = 0; g < NT_ALL; g++) {
        if (g > 0) cp_wait<0>();          // W(g) resident
        __syncthreads();                  // z(g) visible; z(g-1) readers done

        if (g + 1 < NT_ALL && g != NT0 - 1) build_z(g + 1);

        if (g + 1 < NT_ALL) {             // prefetch next W tile (8 chunks/thread)
            const unsigned char* src = g_Wpre + (size_t)(g + 1) * WTILE;
            uint32_t dst = sb + OFF_W + (uint32_t)((g + 1) & 1) * WTILE;
            #pragma unroll
            for (int r = 0; r < 8; r++)
                cpa16(dst + (uint32_t)(r * THREADS + tid) * 16, src + (size_t)(r * THREADS + tid) * 16);
            cp_commit();
        }

        // ---- MMA: warp = (batch bz, obase): MI*16 o x 64 d x 32 k
        {
            const uint32_t wbuf = sb + OFF_W + (uint32_t)(g & 1) * WTILE;
            const uint32_t aA   = wbuf + aRowOff;
            const uint32_t bB   = sb + OFF_Z + (uint32_t)(g & 1) * (2 * ZHALF)
                                + (uint32_t)bz * ZHALF + bRowOff;
            #pragma unroll
            for (uint32_t ks = 0; ks < 4; ks++) {
                uint32_t A[MI][4], B[4][4];
                const uint32_t swA = (((ks << 1) | aHi) ^ l7) << 4;
                const uint32_t swB = (((ks << 1) | bHi) ^ l7) << 4;
                #pragma unroll
                for (int t4 = 0; t4 < MI; t4++) ldmx4(A[t4], aA + (uint32_t)(t4 * 2048) + swA);
                #pragma unroll
                for (int t4 = 0; t4 < 4; t4++) ldmx4(B[t4], bB + (uint32_t)(t4 * 2048) + swB);
                #pragma unroll
                for (int mi = 0; mi < MI; mi++)
                    #pragma unroll
                    for (int t4 = 0; t4 < 4; t4++) {
                        mma_tf32(acc[mi][2*t4],     A[mi], B[t4]);
                        mma_tf32(acc[mi][2*t4 + 1], A[mi], B[t4] + 2);
                    }
            }
        }

        if (g == NT0 - 1) {
            // ======== layer-0 epilogue ========
            __syncthreads();              // all layer-0 MMA smem reads done
            #pragma unroll
            for (int mi = 0; mi < MI; mi++) {
                const int o = obase + mi * 16 + lr;
                const float bias0 = b0g[o], bias1 = b0g[o + 8];
                if (obase + mi * 16 < 64) {   // rows 0..63 -> h (warp-uniform)
                    float* h0 = hs + bz * 4096 + o * 64;
                    float* h1 = h0 + 8 * 64;
                    #pragma unroll
                    for (int nj = 0; nj < 8; nj++) {
                        const int dd = nj * 8 + 2 * lc;
                        h0[dd]     = fmaxf(acc[mi][nj][0] + bias0, 0.0f);
                        h0[dd + 1] = fmaxf(acc[mi][nj][1] + bias0, 0.0f);
                        h1[dd]     = fmaxf(acc[mi][nj][2] + bias1, 0.0f);
                        h1[dd + 1] = fmaxf(acc[mi][nj][3] + bias1, 0.0f);
                    }
                } else {                  // rows 64..127 -> out rows 0..63
                    float s0 = 0.0f, s1 = 0.0f;
                    #pragma unroll
                    for (int nj = 0; nj < 8; nj++) {
                        s0 += fmaxf(acc[mi][nj][0] + bias0, 0.0f)
                            + fmaxf(acc[mi][nj][1] + bias0, 0.0f);
                        s1 += fmaxf(acc[mi][nj][2] + bias1, 0.0f)
                            + fmaxf(acc[mi][nj][3] + bias1, 0.0f);
                    }
                    s0 += __shfl_xor_sync(0xffffffffu, s0, 1);
                    s0 += __shfl_xor_sync(0xffffffffu, s0, 2);
                    s1 += __shfl_xor_sync(0xffffffffu, s1, 1);
                    s1 += __shfl_xor_sync(0xffffffffu, s1, 2);
                    if (lc == 0) {
                        out[(size_t)(bbase + bz) * 192 + (o - 64)]     = s0;
                        out[(size_t)(bbase + bz) * 192 + (o - 64) + 8] = s1;
                    }
                }
            }
            #pragma unroll
            for (int mi = 0; mi < MI; mi++)
                #pragma unroll
                for (int nj = 0; nj < 8; nj++)
                    #pragma unroll
                    for (int q = 0; q < 4; q++) acc[mi][nj][q] = 0.0f;
            __syncthreads();              // h complete before z(NT0) reads it
            build_z(NT0);                 // into buf (NT0&1)=0, safe (last read MMA(NT0-2))
        }
    }

    // ======== layer-1 epilogue: out rows 64..191, direct ========
    #pragma unroll
    for (int mi = 0; mi < MI; mi++) {
        const int o = obase + mi * 16 + lr;
        const float bias0 = b1g[o], bias1 = b1g[o + 8];
        float s0 = 0.0f, s1 = 0.0f;
        #pragma unroll
        for (int nj = 0; nj < 8; nj++) {
            s0 += fmaxf(acc[mi][nj][0] + bias0, 0.0f)
                + fmaxf(acc[mi][nj][1] + bias0, 0.0f);
            s1 += fmaxf(acc[mi][nj][2] + bias1, 0.0f)
                + fmaxf(acc[mi][nj][3] + bias1, 0.0f);
        }
        s0 += __shfl_xor_sync(0xffffffffu, s0, 1);
        s0 += __shfl_xor_sync(0xffffffffu, s0, 2);
        s1 += __shfl_xor_sync(0xffffffffu, s1, 1);
        s1 += __shfl_xor_sync(0xffffffffu, s1, 2);
        if (lc == 0) {
            out[(size_t)(bbase + bz) * 192 + 64 + o]     = s0;
            out[(size_t)(bbase + bz) * 192 + 64 + o + 8] = s1;
        }
    }
}

// ---------------- main kernel: mixed-size grid (tail-wave fill) ----------------
__global__ __launch_bounds__(THREADS, 2)
void cin_mma_kernel(const float* __restrict__ xg,
                    const float* __restrict__ b0g,
                    const float* __restrict__ b1g,
                    float* __restrict__ out)
{
    extern __shared__ __align__(256) unsigned char smem[];
    const uint32_t sb = smem_u32(smem);
    const int bid = blockIdx.x;
    if (bid < GRID_FULL) {
        cin_body<2>(xg, b0g, b1g, out, bid * 2, smem, sb);
    } else {
        cin_body<1>(xg, b0g, b1g, out, GRID_FULL * 2 + (bid - GRID_FULL), smem, sb);
    }
}

// ---------------- launch ----------------
extern "C" void kernel_launch(void* const* d_in, const int* in_sizes, int n_in,
                              void* d_out, int out_size) {
    const float* xg = (const float*)d_in[0];   // (2048,32,64)
    const float* W0 = (const float*)d_in[1];   // (128,1024)
    const float* b0 = (const float*)d_in[2];   // (128)
    const float* W1 = (const float*)d_in[3];   // (128,2048)
    const float* b1 = (const float*)d_in[4];   // (128)
    float* out = (float*)d_out;                // (2048,192)

    prep_kernel<<<1344, 256>>>(W0, W1);

    cudaFuncSetAttribute((const void*)cin_mma_kernel,
                         cudaFuncAttributeMaxDynamicSharedMemorySize, SMEM_TOTAL);
    cin_mma_kernel<<<GRID_FULL + GRID_TAIL, THREADS, SMEM_TOTAL>>>(xg, b0, b1, out);
}

// round 16
// speedup vs baseline: 1.1962x; 1.0090x over previous
#include <cuda_runtime.h>
#include <cstdint>

// ---------------- configuration ----------------
#define THREADS 128
#define NT0     17           // layer-0 tiles (triangle-packed K=544, 32 k each)
#define NT_ALL  81           // + 64 layer-1 tiles (K=2048)
#define WTILE   16384        // 128 rows x 128B, XOR-swizzled tf32
#define ZHALF   8192         // per-batch z: 64 rows x 128B
#define ZSET    16384        // z for both batches (one buffer)
#define GRID_FULL 888        // NB=2 CTAs (3 clean waves on 148 SMs)
#define GRID_TAIL 272        // NB=1 CTAs (tail wave)

// dynamic smem byte offsets (112KB per CTA -> 2 CTAs/SM)
#define OFF_H   0            // 2 * 16384  h fp32 [64][64] per batch
#define OFF_W   32768        // 2 * WTILE  (double-buffered W tile)
#define OFF_Z   65536        // 3 * ZSET   (triple-buffered z; x staged here at init)
#define SMEM_TOTAL 114688

// pre-converted, pre-swizzled W: 81 tf32 tiles (layer-0 triangle-packed)
__device__ __align__(16) unsigned char g_Wpre[NT_ALL * WTILE];

// off-diag block-pair tables (compile-time)
#define PBI(pi) ((pi) < 3 ? 0 : ((pi) < 5 ? 1 : 2))
#define PBJ(pi) ((pi) == 0 ? 1 : ((pi) == 1 || (pi) == 3 ? 2 : 3))

// ---------------- helpers ----------------
static __device__ __forceinline__ uint32_t smem_u32(const void* p) {
    return (uint32_t)__cvta_generic_to_shared(p);
}
static __device__ __forceinline__ void cpa16(uint32_t dst, const void* src) {
    asm volatile("cp.async.cg.shared.global [%0], [%1], 16;" :: "r"(dst), "l"(src));
}
static __device__ __forceinline__ void cp_commit() { asm volatile("cp.async.commit_group;"); }
template <int N>
static __device__ __forceinline__ void cp_wait() { asm volatile("cp.async.wait_group %0;" :: "n"(N)); }

static __device__ __forceinline__ void sts128(uint32_t a, uint32_t r0, uint32_t r1, uint32_t r2, uint32_t r3) {
    asm volatile("st.shared.v4.b32 [%0], {%1, %2, %3, %4};" :: "r"(a), "r"(r0), "r"(r1), "r"(r2), "r"(r3));
}
static __device__ __forceinline__ void ldmx4(uint32_t* r, uint32_t a) {
    asm volatile("ldmatrix.sync.aligned.m8n8.x4.shared.b16 {%0,%1,%2,%3}, [%4];"
        : "=r"(r[0]), "=r"(r[1]), "=r"(r[2]), "=r"(r[3]) : "r"(a));
}
static __device__ __forceinline__ uint32_t f2tf32(float f) {
    uint32_t r; asm("cvt.rna.tf32.f32 %0, %1;" : "=r"(r) : "f"(f)); return r;
}
// m16n8k8 row.col tf32 -> f32, D += A*B (register-pure)
static __device__ __forceinline__ void mma_tf32(float* c, const uint32_t* a, const uint32_t* b) {
    asm("mma.sync.aligned.m16n8k8.row.col.f32.tf32.tf32.f32 "
        "{%0,%1,%2,%3}, {%4,%5,%6,%7}, {%8,%9}, {%0,%1,%2,%3};"
        : "+f"(c[0]), "+f"(c[1]), "+f"(c[2]), "+f"(c[3])
        : "r"(a[0]), "r"(a[1]), "r"(a[2]), "r"(a[3]), "r"(b[0]), "r"(b[1]));
}

// ---------------- prep: triangle-fold L0, round to tf32, swizzle ----------------
// L0 slot map (tile t, slot s):
//  t<12: pi=t>>1, half=t&1: h=8*PBI+4*half+(s>>3), m=8*PBJ+(s&7), W'=W[h,m]+W[m,h]
//  t>=12: q=(t-12)*32+s, blk=q/40, rem=q%40, g=rem>>3, e=rem&7
//         pad iff (g==4 && e>=4) -> W'=0
//         h=8blk+((e<8-g)?g:8-g), m=8blk+((e<8-g)?g+e:e)
//         W' = (h==m) ? W[h,h] : W[h,m]+W[m,h]
__global__ void prep_kernel(const float* __restrict__ W0, const float* __restrict__ W1) {
    int idx = blockIdx.x * 256 + threadIdx.x;      // 0..331775
    if (idx >= 331776) return;
    float w; int o, t, s;
    if (idx < 69632) {                  // layer 0 folded: 128 o x 544 k
        o = idx / 544;
        int k = idx - o * 544;
        t = k >> 5; s = k & 31;
        if (t < 12) {
            int pi = t >> 1, half = t & 1;
            int h = 8 * PBI(pi) + 4 * half + (s >> 3);
            int m = 8 * PBJ(pi) + (s & 7);
            w = W0[o * 1024 + h * 32 + m] + W0[o * 1024 + m * 32 + h];
        } else {
            int q = (t - 12) * 32 + s;
            int blk = q / 40, rem = q % 40;
            int g = rem >> 3, e = rem & 7;
            if (g == 4 && e >= 4) {
                w = 0.0f;
            } else {
                int h = 8 * blk + ((e < 8 - g) ? g : 8 - g);
                int m = 8 * blk + ((e < 8 - g) ? g + e : e);
                w = (h == m) ? W0[o * 1024 + h * 32 + m]
                             : W0[o * 1024 + h * 32 + m] + W0[o * 1024 + m * 32 + h];
            }
        }
    } else {                            // layer 1: 128 o x 2048 k
        int idx2 = idx - 69632;
        o = idx2 >> 11;
        int k = idx2 & 2047;
        t = NT0 + (k >> 5); s = k & 31;
        w = W1[o * 2048 + k];
    }
    uint32_t c = (uint32_t)((s >> 2) & 7);         // 16B chunk within row
    size_t off = (size_t)t * WTILE + (size_t)o * 128
               + (size_t)(((c ^ (o & 7)) << 4) + (s & 3) * 4);
    *(uint32_t*)(g_Wpre + off) = f2tf32(w);
}

// ---------------- static L0 z slot value (all indices are template constants) ----
template <int T, int S>
static __device__ __forceinline__ uint32_t z0_val(const float* xmc) {
    if constexpr (T < 12) {
        constexpr int pi = T >> 1, half = T & 1;
        constexpr int h = 8 * PBI(pi) + 4 * half + (S >> 3);
        constexpr int m = 8 * PBJ(pi) + (S & 7);
        return f2tf32(xmc[h] * xmc[m]);
    } else {
        constexpr int q = (T - 12) * 32 + S;
        constexpr int blk = q / 40, rem = q % 40;
        constexpr int g = rem >> 3, e = rem & 7;
        if constexpr (g == 4 && e >= 4) {
            return 0u;                              // pad slot (W'=0)
        } else {
            constexpr int h = 8 * blk + ((e < 8 - g) ? g : 8 - g);
            constexpr int m = 8 * blk + ((e < 8 - g) ? g + e : e);
            return f2tf32(xmc[h] * xmc[m]);
        }
    }
}

template <int T, int C4>
static __device__ __forceinline__ void z0_chunk(const float* xmc, uint32_t zb, uint32_t d7) {
    uint32_t t0 = z0_val<T, 4 * C4 + 0>(xmc);
    uint32_t t1 = z0_val<T, 4 * C4 + 1>(xmc);
    uint32_t t2 = z0_val<T, 4 * C4 + 2>(xmc);
    uint32_t t3 = z0_val<T, 4 * C4 + 3>(xmc);
    sts128(zb + (((uint32_t)C4 ^ d7) << 4), t0, t1, t2, t3);
}

template <int T>
static __device__ __forceinline__ void build_z0_t(const float* xmc, uint32_t zb, uint32_t d7) {
    z0_chunk<T, 0>(xmc, zb, d7);
    z0_chunk<T, 1>(xmc, zb, d7);
    z0_chunk<T, 2>(xmc, zb, d7);
    z0_chunk<T, 3>(xmc, zb, d7);
    z0_chunk<T, 4>(xmc, zb, d7);
    z0_chunk<T, 5>(xmc, zb, d7);
    z0_chunk<T, 6>(xmc, zb, d7);
    z0_chunk<T, 7>(xmc, zb, d7);
}

// ---------------- body ----------------
template <int NBATCH>
static __device__ __forceinline__ void cin_body(
    const float* __restrict__ xg, const float* __restrict__ b0g,
    const float* __restrict__ b1g, float* __restrict__ out,
    int bbase, unsigned char* smem, uint32_t sb)
{
    constexpr int MI = 2 * NBATCH;      // 16-row acc tiles per warp
    const int tid  = threadIdx.x;
    const int wid  = tid >> 5;
    const int lane = tid & 31;
    const int lr   = lane >> 2;
    const int lc   = lane & 3;

    const int bz    = (NBATCH == 2) ? (wid >> 1) : 0;
    const int obase = (NBATCH == 2) ? ((wid & 1) * 64) : (wid * 32);

    // swizzled ldmatrix addressing
    const uint32_t l7  = (uint32_t)(lane & 7);
    const uint32_t aHi = (uint32_t)((lane >> 4) & 1);
    const uint32_t bHi = (uint32_t)((lane >> 3) & 1);
    const uint32_t aRowOff = (uint32_t)((obase + (lane & 15)) * 128);
    const uint32_t bRowOff = (uint32_t)(((lane & 7) + ((lane & 16) >> 1)) * 128);

    float* hs = (float*)(smem + OFF_H);
    float* xstage = (float*)(smem + OFF_Z);   // x staged in z buf0 region at init

    // initial loads: x (NBATCH*8KB -> z region) + W tile 0 (16KB)
    {
        const char* src = (const char*)(xg + (size_t)bbase * 2048);
        #pragma unroll
        for (int r = 0; r < NBATCH * 4; r++)
            cpa16(sb + OFF_Z + (uint32_t)(r * THREADS + tid) * 16, src + (size_t)(r * THREADS + tid) * 16);
        #pragma unroll
        for (int r = 0; r < 8; r++)
            cpa16(sb + OFF_W + (uint32_t)(r * THREADS + tid) * 16, g_Wpre + (size_t)(r * THREADS + tid) * 16);
        cp_commit();
    }

    // z producer mapping: thread -> (batch bzt, d)
    const int d   = tid & 63;
    const int bzt = (NBATCH == 2) ? (tid >> 6) : 0;
    const bool zact = (NBATCH == 2) || (tid < 64);
    const uint32_t d7 = (uint32_t)(d & 7);

    cp_wait<0>();
    __syncthreads();

    // register-cached x values (all 32 rows at this thread's d; both layers)
    float xmc[32];
    if (zact) {
        #pragma unroll
        for (int j = 0; j < 32; j++) xmc[j] = xstage[bzt * 2048 + j * 64 + d];
    }
    __syncthreads();    // all xmc reads done before z builds overwrite staging

    // build z tile j into buffer j%3. Never touches acc.
    auto build_z = [&](int j) {
        if (!zact) return;
        const uint32_t zb = sb + OFF_Z + (uint32_t)(j % 3) * ZSET + (uint32_t)bzt * ZHALF
                          + (uint32_t)(d * 128);
        if (j < NT0) {
            switch (j) {
                case 0:  build_z0_t<0>(xmc, zb, d7); break;
                case 1:  build_z0_t<1>(xmc, zb, d7); break;
                case 2:  build_z0_t<2>(xmc, zb, d7); break;
                case 3:  build_z0_t<3>(xmc, zb, d7); break;
                case 4:  build_z0_t<4>(xmc, zb, d7); break;
                case 5:  build_z0_t<5>(xmc, zb, d7); break;
                case 6:  build_z0_t<6>(xmc, zb, d7); break;
                case 7:  build_z0_t<7>(xmc, zb, d7); break;
                case 8:  build_z0_t<8>(xmc, zb, d7); break;
                case 9:  build_z0_t<9>(xmc, zb, d7); break;
                case 10: build_z0_t<10>(xmc, zb, d7); break;
                case 11: build_z0_t<11>(xmc, zb, d7); break;
                case 12: build_z0_t<12>(xmc, zb, d7); break;
                case 13: build_z0_t<13>(xmc, zb, d7); break;
                case 14: build_z0_t<14>(xmc, zb, d7); break;
                case 15: build_z0_t<15>(xmc, zb, d7); break;
                default: build_z0_t<16>(xmc, zb, d7); break;
            }
        } else {
            const float xh = hs[bzt * 4096 + (j - NT0) * 64 + d];
            #pragma unroll
            for (int c4 = 0; c4 < 8; c4++) {
                uint32_t t0 = f2tf32(xh * xmc[4 * c4 + 0]);
                uint32_t t1 = f2tf32(xh * xmc[4 * c4 + 1]);
                uint32_t t2 = f2tf32(xh * xmc[4 * c4 + 2]);
                uint32_t t3 = f2tf32(xh * xmc[4 * c4 + 3]);
                sts128(zb + (((uint32_t)c4 ^ d7) << 4), t0, t1, t2, t3);
            }
        }
    };

    float acc[MI][8][4];            // statically indexed
    #pragma unroll
    for (int mi = 0; mi < MI; mi++)
        #pragma unroll
        for (int nj = 0; nj < 8; nj++)
            #pragma unroll
            for (int q = 0; q < 4; q++) acc[mi][nj][q] = 0.0f;

    build_z(0);          // buf 0 (overwrites x staging; xmc already loaded)
    build_z(1);          // buf 1

    for (int g = 0; g < NT_ALL; g++) {
        if (g > 0) cp_wait<0>();          // W(g) resident
        __syncthreads();                  // z(g)/z(g+1) visible; buf (g+2)%3 readers done

        // ---- MMA block FIRST (z(g) built two iters ago; post-barrier path = ldmx only)
        {
            const uint32_t wbuf = sb + OFF_W + (uint32_t)(g & 1) * WTILE;
            const uint32_t aA   = wbuf + aRowOff;
            const uint32_t bB   = sb + OFF_Z + (uint32_t)(g % 3) * ZSET
                                + (uint32_t)bz * ZHALF + bRowOff;
            #pragma unroll
            for (uint32_t ks = 0; ks < 4; ks++) {
                uint32_t A[MI][4], B[4][4];
                const uint32_t swA = (((ks << 1) | aHi) ^ l7) << 4;
                const uint32_t swB = (((ks << 1) | bHi) ^ l7) << 4;
                #pragma unroll
                for (int t4 = 0; t4 < MI; t4++) ldmx4(A[t4], aA + (uint32_t)(t4 * 2048) + swA);
                #pragma unroll
                for (int t4 = 0; t4 < 4; t4++) ldmx4(B[t4], bB + (uint32_t)(t4 * 2048) + swB);
                if (ks == 0 && g + 1 < NT_ALL) {   // W(g+1) prefetch under the mma stream
                    const unsigned char* src = g_Wpre + (size_t)(g + 1) * WTILE;
                    uint32_t dst = sb + OFF_W + (uint32_t)((g + 1) & 1) * WTILE;
                    #pragma unroll
                    for (int r = 0; r < 8; r++)
                        cpa16(dst + (uint32_t)(r * THREADS + tid) * 16, src + (size_t)(r * THREADS + tid) * 16);
                    cp_commit();
                }
                #pragma unroll
                for (int mi = 0; mi < MI; mi++)
                    #pragma unroll
                    for (int t4 = 0; t4 < 4; t4++) {
                        mma_tf32(acc[mi][2*t4],     A[mi], B[t4]);
                        mma_tf32(acc[mi][2*t4 + 1], A[mi], B[t4] + 2);
                    }
            }
        }

        // ---- build z(g+2) after MMA: not needed for 2 more iters (slack)
        {
            const int j = g + 2;
            if (j < NT_ALL && j != NT0 && j != NT0 + 1) build_z(j);
        }

        if (g == NT0 - 1) {
            // ======== layer-0 epilogue ========
            __syncthreads();              // all layer-0 MMA smem reads done
            #pragma unroll
            for (int mi = 0; mi < MI; mi++) {
                const int o = obase + mi * 16 + lr;
                const float bias0 = b0g[o], bias1 = b0g[o + 8];
                if (obase + mi * 16 < 64) {   // rows 0..63 -> h (warp-uniform)
                    float* h0 = hs + bz * 4096 + o * 64;
                    float* h1 = h0 + 8 * 64;
                    #pragma unroll
                    for (int nj = 0; nj < 8; nj++) {
                        const int dd = nj * 8 + 2 * lc;
                        h0[dd]     = fmaxf(acc[mi][nj][0] + bias0, 0.0f);
                        h0[dd + 1] = fmaxf(acc[mi][nj][1] + bias0, 0.0f);
                        h1[dd]     = fmaxf(acc[mi][nj][2] + bias1, 0.0f);
                        h1[dd + 1] = fmaxf(acc[mi][nj][3] + bias1, 0.0f);
                    }
                } else {                  // rows 64..127 -> out rows 0..63
                    float s0 = 0.0f, s1 = 0.0f;
                    #pragma unroll
                    for (int nj = 0; nj < 8; nj++) {
                        s0 += fmaxf(acc[mi][nj][0] + bias0, 0.0f)
                            + fmaxf(acc[mi][nj][1] + bias0, 0.0f);
                        s1 += fmaxf(acc[mi][nj][2] + bias1, 0.0f)
                            + fmaxf(acc[mi][nj][3] + bias1, 0.0f);
                    }
                    s0 += __shfl_xor_sync(0xffffffffu, s0, 1);
                    s0 += __shfl_xor_sync(0xffffffffu, s0, 2);
                    s1 += __shfl_xor_sync(0xffffffffu, s1, 1);
                    s1 += __shfl_xor_sync(0xffffffffu, s1, 2);
                    if (lc == 0) {
                        out[(size_t)(bbase + bz) * 192 + (o - 64)]     = s0;
                        out[(size_t)(bbase + bz) * 192 + (o - 64) + 8] = s1;
                    }
                }
            }
            #pragma unroll
            for (int mi = 0; mi < MI; mi++)
                #pragma unroll
                for (int nj = 0; nj < 8; nj++)
                    #pragma unroll
                    for (int q = 0; q < 4; q++) acc[mi][nj][q] = 0.0f;
            __syncthreads();              // h complete before L1 z builds read it
            build_z(NT0);                 // buf NT0%3=2: readers MMA(NT0-3) done
            build_z(NT0 + 1);             // buf 0: readers MMA(NT0-2) done
        }
    }

    // ======== layer-1 epilogue: out rows 64..191, direct ========
    #pragma unroll
    for (int mi = 0; mi < MI; mi++) {
        const int o = obase + mi * 16 + lr;
        const float bias0 = b1g[o], bias1 = b1g[o + 8];
        float s0 = 0.0f, s1 = 0.0f;
        #pragma unroll
        for (int nj = 0; nj < 8; nj++) {
            s0 += fmaxf(acc[mi][nj][0] + bias0, 0.0f)
                + fmaxf(acc[mi][nj][1] + bias0, 0.0f);
            s1 += fmaxf(acc[mi][nj][2] + bias1, 0.0f)
                + fmaxf(acc[mi][nj][3] + bias1, 0.0f);
        }
        s0 += __shfl_xor_sync(0xffffffffu, s0, 1);
        s0 += __shfl_xor_sync(0xffffffffu, s0, 2);
        s1 += __shfl_xor_sync(0xffffffffu, s1, 1);
        s1 += __shfl_xor_sync(0xffffffffu, s1, 2);
        if (lc == 0) {
            out[(size_t)(bbase + bz) * 192 + 64 + o]     = s0;
            out[(size_t)(bbase + bz) * 192 + 64 + o + 8] = s1;
        }
    }
}

// ---------------- main kernel: mixed-size grid (tail-wave fill) ----------------
__global__ __launch_bounds__(THREADS, 2)
void cin_mma_kernel(const float* __restrict__ xg,
                    const float* __restrict__ b0g,
                    const float* __restrict__ b1g,
                    float* __restrict__ out)
{
    extern __shared__ __align__(256) unsigned char smem[];
    const uint32_t sb = smem_u32(smem);
    const int bid = blockIdx.x;
    if (bid < GRID_FULL) {
        cin_body<2>(xg, b0g, b1g, out, bid * 2, smem, sb);
    } else {
        cin_body<1>(xg, b0g, b1g, out, GRID_FULL * 2 + (bid - GRID_FULL), smem, sb);
    }
}

// ---------------- launch ----------------
extern "C" void kernel_launch(void* const* d_in, const int* in_sizes, int n_in,
                              void* d_out, int out_size) {
    const float* xg = (const float*)d_in[0];   // (2048,32,64)
    const float* W0 = (const float*)d_in[1];   // (128,1024)
    const float* b0 = (const float*)d_in[2];   // (128)
    const float* W1 = (const float*)d_in[3];   // (128,2048)
    const float* b1 = (const float*)d_in[4];   // (128)
    float* out = (float*)d_out;                // (2048,192)

    prep_kernel<<<1296, 256>>>(W0, W1);

    cudaFuncSetAttribute((const void*)cin_mma_kernel,
                         cudaFuncAttributeMaxDynamicSharedMemorySize, SMEM_TOTAL);
    cin_mma_kernel<<<GRID_FULL + GRID_TAIL, THREADS, SMEM_TOTAL>>>(xg, b0, b1, out);
}